// round 1
// baseline (speedup 1.0000x reference)
#include <cuda_runtime.h>
#include <cuda_fp16.h>
#include <stdint.h>

#define NTOK   49
#define DIM    512
#define HEADS  16
#define HDIM   32
#define BATCH  4096
#define MROWS  200704          // BATCH*NTOK
#define KD     512
#define NCOLS  1536            // q|k|v concatenated
#define SCALE  0.17677669529663687f   // 1/sqrt(32)

// ---------------- scratch (static device arrays; no allocation) ----------------
__device__ __half g_H16 [102760448];   // hidden fp16 [MROWS][512]
__device__ __half g_WT16[786432];      // weights [n=1536][k=512] fp16 (transposed)
__device__ float  g_biasf[1536];       // packed bq|bk|bv
__device__ __half g_Q[102760448];      // [b][h][tok][d]
__device__ __half g_K[102760448];
__device__ __half g_V[102760448];
__device__ float  g_biasHIJ[38416];    // [h][i][j] gathered rel-pos bias

// ---------------- helpers ----------------
__device__ __forceinline__ uint32_t smem_u32(const void* p){
    return (uint32_t)__cvta_generic_to_shared(p);
}
__device__ __forceinline__ void cp_async16(void* s, const void* g){
    asm volatile("cp.async.cg.shared.global [%0], [%1], 16;\n"
                 :: "r"(smem_u32(s)), "l"(g));
}
__device__ __forceinline__ void ldsm_x4(uint32_t* r, const void* p){
    asm volatile("ldmatrix.sync.aligned.m8n8.x4.shared.b16 {%0,%1,%2,%3}, [%4];"
        : "=r"(r[0]),"=r"(r[1]),"=r"(r[2]),"=r"(r[3]) : "r"(smem_u32(p)));
}
__device__ __forceinline__ void ldsm_x2(uint32_t* r, const void* p){
    asm volatile("ldmatrix.sync.aligned.m8n8.x2.shared.b16 {%0,%1}, [%2];"
        : "=r"(r[0]),"=r"(r[1]) : "r"(smem_u32(p)));
}
__device__ __forceinline__ void mma16816(float* c, const uint32_t* a, const uint32_t* b){
    asm volatile("mma.sync.aligned.m16n8k16.row.col.f32.f16.f16.f32 "
        "{%0,%1,%2,%3},{%4,%5,%6,%7},{%8,%9},{%0,%1,%2,%3};"
        : "+f"(c[0]),"+f"(c[1]),"+f"(c[2]),"+f"(c[3])
        : "r"(a[0]),"r"(a[1]),"r"(a[2]),"r"(a[3]),"r"(b[0]),"r"(b[1]));
}

// ---------------- K0: convert hidden to fp16 ----------------
__global__ void cvt_hidden(const float* __restrict__ src){
    size_t i = (size_t)blockIdx.x * blockDim.x + threadIdx.x;   // 12,845,056 threads, 8 elems each
    const float4* s4 = reinterpret_cast<const float4*>(src);
    float4 f0 = s4[i*2], f1 = s4[i*2+1];
    __half2 h[4];
    h[0] = __floats2half2_rn(f0.x, f0.y);
    h[1] = __floats2half2_rn(f0.z, f0.w);
    h[2] = __floats2half2_rn(f1.x, f1.y);
    h[3] = __floats2half2_rn(f1.z, f1.w);
    *reinterpret_cast<uint4*>(&g_H16[i*8]) = *reinterpret_cast<uint4*>(h);
}

// ---------------- K0b: weights -> [n][k] fp16, pack biases ----------------
__global__ void prep_w(const float* __restrict__ Wq, const float* __restrict__ bq,
                       const float* __restrict__ Wk, const float* __restrict__ bk,
                       const float* __restrict__ Wv, const float* __restrict__ bv){
    int t = blockIdx.x*256 + threadIdx.x;
    if (t < 786432){
        int n = t >> 9, k = t & 511;
        int w = n >> 9, col = n & 511;
        const float* W = (w==0)?Wq:((w==1)?Wk:Wv);
        g_WT16[t] = __float2half(W[k*512 + col]);
    }
    if (t < 1536){
        int w = t >> 9, c = t & 511;
        g_biasf[t] = ((w==0)?bq:((w==1)?bk:bv))[c];
    }
}

// ---------------- K0c: gather relative position bias [h][i][j] ----------------
__global__ void prep_bias(const float* __restrict__ table, const int* __restrict__ idx){
    int t = blockIdx.x*256 + threadIdx.x;
    if (t < 38416){
        int h = t / 2401, e = t - h*2401;
        g_biasHIJ[t] = table[idx[e]*HEADS + h];
    }
}

// ---------------- K1: QKV GEMM (fp16 HMMA, 128x128x64 tiles) ----------------
#define BM 128
#define BN 128
#define BK 64
#define LDT 72    // BK + 8 halfs padding -> conflict-free ldmatrix

__global__ void __launch_bounds__(256,2) gemm_qkv(){
    extern __shared__ __align__(16) __half sm[];
    __half* As = sm;                          // [2][BM][LDT]
    __half* Bs = sm + 2*BM*LDT;               // [2][BN][LDT]
    const int tid  = threadIdx.x;
    const int lane = tid & 31, warp = tid >> 5;
    const int wm = (warp >> 2) * 64;          // 2 warps in M
    const int wn = (warp & 3) * 32;           // 4 warps in N
    const size_t rowA = (size_t)blockIdx.y * BM;   // M tiles on .y (N fastest -> A-tile L2 reuse)
    const size_t rowB = (size_t)blockIdx.x * BN;
    const __half* gA = g_H16  + rowA * KD;
    const __half* gB = g_WT16 + rowB * KD;

    auto load_tile = [&](int buf, int kc){
        #pragma unroll
        for (int i=0;i<4;i++){
            int c = tid + i*256;
            int r = c >> 3, o = (c & 7) * 8;
            cp_async16(&As[buf*(BM*LDT) + r*LDT + o], &gA[(size_t)r*KD + kc + o]);
        }
        #pragma unroll
        for (int i=0;i<4;i++){
            int c = tid + i*256;
            int r = c >> 3, o = (c & 7) * 8;
            cp_async16(&Bs[buf*(BN*LDT) + r*LDT + o], &gB[(size_t)r*KD + kc + o]);
        }
        asm volatile("cp.async.commit_group;\n" ::);
    };

    float acc[4][4][4];
    #pragma unroll
    for (int i=0;i<4;i++)
        #pragma unroll
        for (int j=0;j<4;j++)
            #pragma unroll
            for (int q=0;q<4;q++) acc[i][j][q] = 0.f;

    load_tile(0, 0);
    for (int ch=0; ch<8; ch++){
        if (ch < 7){
            load_tile((ch+1)&1, (ch+1)*BK);
            asm volatile("cp.async.wait_group 1;\n" ::);
        } else {
            asm volatile("cp.async.wait_group 0;\n" ::);
        }
        __syncthreads();
        const __half* At = &As[(ch&1)*(BM*LDT)];
        const __half* Bt = &Bs[(ch&1)*(BN*LDT)];
        #pragma unroll
        for (int kk=0; kk<BK; kk+=16){
            uint32_t a[4][4], b[4][2];
            #pragma unroll
            for (int mi=0;mi<4;mi++)
                ldsm_x4(a[mi], &At[(wm + mi*16 + (lane&15))*LDT + kk + (lane>>4)*8]);
            #pragma unroll
            for (int ni=0;ni<4;ni++)
                ldsm_x2(b[ni], &Bt[(wn + ni*8 + (lane&7))*LDT + kk + ((lane>>3)&1)*8]);
            #pragma unroll
            for (int mi=0;mi<4;mi++)
                #pragma unroll
                for (int ni=0;ni<4;ni++)
                    mma16816(acc[mi][ni], a[mi], b[ni]);
        }
        __syncthreads();
    }

    // epilogue: add bias, convert to fp16, scatter into [b][h][tok][d]
    const int rr = lane >> 2, cb = (lane & 3) * 2;
    #pragma unroll
    for (int mi=0;mi<4;mi++){
        int m0 = (int)rowA + wm + mi*16 + rr;
        int m1 = m0 + 8;
        int b0 = m0 / 49, t0 = m0 - b0*49;
        int b1 = m1 / 49, t1 = m1 - b1*49;
        #pragma unroll
        for (int ni=0;ni<4;ni++){
            int n = (int)rowB + wn + ni*8 + cb;
            int which = n >> 9, hh = (n >> 5) & 15, d = n & 31;
            float ba = g_biasf[n], bb = g_biasf[n+1];
            __half* dst = (which==0) ? g_Q : ((which==1) ? g_K : g_V);
            __half2 v01 = __floats2half2_rn(acc[mi][ni][0] + ba, acc[mi][ni][1] + bb);
            __half2 v23 = __floats2half2_rn(acc[mi][ni][2] + ba, acc[mi][ni][3] + bb);
            size_t a0 = (((size_t)b0*HEADS + hh)*49 + t0)*32 + d;
            size_t a1 = (((size_t)b1*HEADS + hh)*49 + t1)*32 + d;
            *reinterpret_cast<__half2*>(&dst[a0]) = v01;
            *reinterpret_cast<__half2*>(&dst[a1]) = v23;
        }
    }
}

// ---------------- K2: fused windowed attention ----------------
#define GROUP 8   // windows per block (same head -> bias tile reused)

__global__ void __launch_bounds__(128) attn(float* __restrict__ out){
    const int h   = blockIdx.y;
    const int wg  = blockIdx.x;
    const int tid = threadIdx.x, lane = tid & 31, warp = tid >> 5;

    __shared__ __align__(16) float  sBias[2401];
    __shared__ __align__(16) __half sQ [64*40];   // rows padded to 64, stride 40 halfs
    __shared__ __align__(16) __half sK [56*40];
    __shared__ __align__(16) __half sVT[32*72];   // V transposed: [d][tok], stride 72

    for (int e=tid; e<2401;  e+=128) sBias[e] = g_biasHIJ[h*2401 + e];
    for (int e=tid; e<64*40; e+=128) sQ[e]  = __float2half(0.f);
    for (int e=tid; e<56*40; e+=128) sK[e]  = __float2half(0.f);
    for (int e=tid; e<32*72; e+=128) sVT[e] = __float2half(0.f);

    const int rr = lane >> 2, cb = (lane & 3) * 2;
    const int row0 = warp*16 + rr;                 // row1 = row0 + 8

    for (int wi=0; wi<GROUP; wi++){
        const int b = wg*GROUP + wi;
        const size_t base = ((size_t)b*HEADS + h) * (49*32);
        __syncthreads();   // previous window's compute done before overwrite
        const __half2* q2 = reinterpret_cast<const __half2*>(g_Q + base);
        const __half2* k2 = reinterpret_cast<const __half2*>(g_K + base);
        const __half2* v2 = reinterpret_cast<const __half2*>(g_V + base);
        for (int e=tid; e<784; e+=128){            // 49 toks * 16 half2
            int t = e >> 4, c = (e & 15) * 2;
            *reinterpret_cast<__half2*>(&sQ[t*40 + c]) = q2[e];
            *reinterpret_cast<__half2*>(&sK[t*40 + c]) = k2[e];
            __half2 v = v2[e];
            sVT[ c   *72 + t] = __low2half(v);
            sVT[(c+1)*72 + t] = __high2half(v);
        }
        __syncthreads();

        // scores = Q K^T  (m16 per warp, n=56 padded, k=32)
        uint32_t aq[2][4];
        ldsm_x4(aq[0], &sQ[(warp*16 + (lane&15))*40 +      (lane>>4)*8]);
        ldsm_x4(aq[1], &sQ[(warp*16 + (lane&15))*40 + 16 + (lane>>4)*8]);
        float sc[7][4];
        #pragma unroll
        for (int ni=0;ni<7;ni++){ sc[ni][0]=sc[ni][1]=sc[ni][2]=sc[ni][3]=0.f; }
        #pragma unroll
        for (int ni=0;ni<7;ni++){
            uint32_t bk0[2], bk1[2];
            ldsm_x2(bk0, &sK[(ni*8 + (lane&7))*40 +      ((lane>>3)&1)*8]);
            ldsm_x2(bk1, &sK[(ni*8 + (lane&7))*40 + 16 + ((lane>>3)&1)*8]);
            mma16816(sc[ni], aq[0], bk0);
            mma16816(sc[ni], aq[1], bk1);
        }

        // scale + bias + mask, row softmax (register-resident)
        float m0=-1e30f, m1=-1e30f;
        #pragma unroll
        for (int ni=0;ni<7;ni++){
            #pragma unroll
            for (int c=0;c<2;c++){
                int col = ni*8 + cb + c;
                if (col < 49){
                    float bi0 = (row0   < 49) ? sBias[ row0   *49 + col] : 0.f;
                    float bi1 = (row0+8 < 49) ? sBias[(row0+8)*49 + col] : 0.f;
                    sc[ni][c]   = sc[ni][c]  *SCALE + bi0;
                    sc[ni][2+c] = sc[ni][2+c]*SCALE + bi1;
                } else {
                    sc[ni][c] = -1e30f; sc[ni][2+c] = -1e30f;
                }
                m0 = fmaxf(m0, sc[ni][c]);
                m1 = fmaxf(m1, sc[ni][2+c]);
            }
        }
        m0 = fmaxf(m0, __shfl_xor_sync(0xffffffffu, m0, 1));
        m0 = fmaxf(m0, __shfl_xor_sync(0xffffffffu, m0, 2));
        m1 = fmaxf(m1, __shfl_xor_sync(0xffffffffu, m1, 1));
        m1 = fmaxf(m1, __shfl_xor_sync(0xffffffffu, m1, 2));
        float s0=0.f, s1=0.f;
        #pragma unroll
        for (int ni=0;ni<7;ni++){
            #pragma unroll
            for (int c=0;c<2;c++){
                float p0 = __expf(sc[ni][c]   - m0);
                float p1 = __expf(sc[ni][2+c] - m1);
                sc[ni][c] = p0; sc[ni][2+c] = p1;
                s0 += p0; s1 += p1;
            }
        }
        s0 += __shfl_xor_sync(0xffffffffu, s0, 1);
        s0 += __shfl_xor_sync(0xffffffffu, s0, 2);
        s1 += __shfl_xor_sync(0xffffffffu, s1, 1);
        s1 += __shfl_xor_sync(0xffffffffu, s1, 2);

        // ctx = P V : reuse score C-fragments directly as A-fragments
        float o[4][4];
        #pragma unroll
        for (int ni=0;ni<4;ni++){ o[ni][0]=o[ni][1]=o[ni][2]=o[ni][3]=0.f; }
        #pragma unroll
        for (int ks=0; ks<4; ks++){
            uint32_t pa[4];
            int f0 = 2*ks, f1 = 2*ks + 1;
            __half2 t0 = __floats2half2_rn(sc[f0][0], sc[f0][1]);
            __half2 t1 = __floats2half2_rn(sc[f0][2], sc[f0][3]);
            pa[0] = *reinterpret_cast<uint32_t*>(&t0);
            pa[1] = *reinterpret_cast<uint32_t*>(&t1);
            if (f1 < 7){
                __half2 t2 = __floats2half2_rn(sc[f1][0], sc[f1][1]);
                __half2 t3 = __floats2half2_rn(sc[f1][2], sc[f1][3]);
                pa[2] = *reinterpret_cast<uint32_t*>(&t2);
                pa[3] = *reinterpret_cast<uint32_t*>(&t3);
            } else { pa[2] = 0u; pa[3] = 0u; }
            #pragma unroll
            for (int ni=0;ni<4;ni++){
                uint32_t bv_[2];
                ldsm_x2(bv_, &sVT[(ni*8 + (lane&7))*72 + ks*16 + ((lane>>3)&1)*8]);
                mma16816(o[ni], pa, bv_);
            }
        }

        float inv0 = 1.f / s0, inv1 = 1.f / s1;
        #pragma unroll
        for (int ni=0;ni<4;ni++){
            int d = ni*8 + cb;
            if (row0 < 49){
                float2 r = make_float2(o[ni][0]*inv0, o[ni][1]*inv0);
                *reinterpret_cast<float2*>(&out[((size_t)b*49 + row0)*512 + h*32 + d]) = r;
            }
            if (row0 + 8 < 49){
                float2 r = make_float2(o[ni][2]*inv1, o[ni][3]*inv1);
                *reinterpret_cast<float2*>(&out[((size_t)b*49 + row0 + 8)*512 + h*32 + d]) = r;
            }
        }
    }
}

// ---------------- launch ----------------
extern "C" void kernel_launch(void* const* d_in, const int* in_sizes, int n_in,
                              void* d_out, int out_size){
    const float* hidden = (const float*)d_in[0];
    const float* Wq = (const float*)d_in[1];
    const float* bq = (const float*)d_in[2];
    const float* Wk = (const float*)d_in[3];
    const float* bk = (const float*)d_in[4];
    const float* Wv = (const float*)d_in[5];
    const float* bv = (const float*)d_in[6];
    const float* table = (const float*)d_in[7];
    const int*   idx   = (const int*)  d_in[8];
    float* out = (float*)d_out;

    const int gemm_smem = 2*(BM*LDT + BN*LDT)*(int)sizeof(__half);   // 73728
    cudaFuncSetAttribute(gemm_qkv, cudaFuncAttributeMaxDynamicSharedMemorySize, gemm_smem);

    cvt_hidden<<<50176, 256>>>(hidden);
    prep_w    <<<3072,  256>>>(Wq, bq, Wk, bk, Wv, bv);
    prep_bias <<<151,   256>>>(table, idx);
    gemm_qkv  <<<dim3(12, 1568), 256, gemm_smem>>>();   // N-tiles fastest -> A-tile L2 reuse
    attn      <<<dim3(512, 16), 128>>>(out);
}

// round 7
// speedup vs baseline: 1.0360x; 1.0360x over previous
#include <cuda_runtime.h>
#include <cuda_fp16.h>
#include <stdint.h>

#define NTOK   49
#define DIM    512
#define HEADS  16
#define HDIM   32
#define BATCH  4096
#define MROWS  200704          // BATCH*NTOK
#define KD     512
#define SCALE  0.17677669529663687f   // 1/sqrt(32)

// ---------------- scratch (static device arrays; no allocation) ----------------
__device__ __half g_H16 [102760448];   // hidden fp16 [MROWS][512]
__device__ __half g_WT16[786432];      // weights [n=1536][k=512] fp16 (transposed)
__device__ float  g_biasf[1536];       // packed bq|bk|bv
__device__ __half g_Q[102760448];      // [b][h][tok][d]
__device__ __half g_K[102760448];
__device__ __half g_V[102760448];
__device__ float  g_biasHIJ[38416];    // [h][i][j] gathered rel-pos bias

// ---------------- helpers ----------------
__device__ __forceinline__ uint32_t smem_u32(const void* p){
    return (uint32_t)__cvta_generic_to_shared(p);
}
__device__ __forceinline__ void cp_async16(void* s, const void* g){
    asm volatile("cp.async.cg.shared.global [%0], [%1], 16;\n"
                 :: "r"(smem_u32(s)), "l"(g));
}
__device__ __forceinline__ void ldsm_x4(uint32_t* r, const void* p){
    asm volatile("ldmatrix.sync.aligned.m8n8.x4.shared.b16 {%0,%1,%2,%3}, [%4];"
        : "=r"(r[0]),"=r"(r[1]),"=r"(r[2]),"=r"(r[3]) : "r"(smem_u32(p)));
}
__device__ __forceinline__ void ldsm_x4t(uint32_t* r, const void* p){
    asm volatile("ldmatrix.sync.aligned.m8n8.x4.trans.shared.b16 {%0,%1,%2,%3}, [%4];"
        : "=r"(r[0]),"=r"(r[1]),"=r"(r[2]),"=r"(r[3]) : "r"(smem_u32(p)));
}
__device__ __forceinline__ void ldsm_x2(uint32_t* r, const void* p){
    asm volatile("ldmatrix.sync.aligned.m8n8.x2.shared.b16 {%0,%1}, [%2];"
        : "=r"(r[0]),"=r"(r[1]) : "r"(smem_u32(p)));
}
__device__ __forceinline__ void mma16816(float* c, const uint32_t* a, const uint32_t* b){
    asm volatile("mma.sync.aligned.m16n8k16.row.col.f32.f16.f16.f32 "
        "{%0,%1,%2,%3},{%4,%5,%6,%7},{%8,%9},{%0,%1,%2,%3};"
        : "+f"(c[0]),"+f"(c[1]),"+f"(c[2]),"+f"(c[3])
        : "r"(a[0]),"r"(a[1]),"r"(a[2]),"r"(a[3]),"r"(b[0]),"r"(b[1]));
}

// ---------------- K0: convert hidden to fp16 ----------------
__global__ void cvt_hidden(const float* __restrict__ src){
    size_t i = (size_t)blockIdx.x * blockDim.x + threadIdx.x;
    const float4* s4 = reinterpret_cast<const float4*>(src);
    float4 f0 = s4[i*2], f1 = s4[i*2+1];
    __half2 h[4];
    h[0] = __floats2half2_rn(f0.x, f0.y);
    h[1] = __floats2half2_rn(f0.z, f0.w);
    h[2] = __floats2half2_rn(f1.x, f1.y);
    h[3] = __floats2half2_rn(f1.z, f1.w);
    *reinterpret_cast<uint4*>(&g_H16[i*8]) = *reinterpret_cast<uint4*>(h);
}

// ---------------- K0b: weights transpose + bias pack + rel-pos gather ----------------
__global__ void prep_all(const float* __restrict__ Wq, const float* __restrict__ bq,
                         const float* __restrict__ Wk, const float* __restrict__ bk,
                         const float* __restrict__ Wv, const float* __restrict__ bv,
                         const float* __restrict__ table, const int* __restrict__ idx){
    int t = blockIdx.x*256 + threadIdx.x;
    if (t < 786432){
        int n = t >> 9, k = t & 511;
        int w = n >> 9, col = n & 511;
        const float* W = (w==0)?Wq:((w==1)?Wk:Wv);
        g_WT16[t] = __float2half(W[k*512 + col]);
    }
    if (t < 1536){
        int w = t >> 9, c = t & 511;
        g_biasf[t] = ((w==0)?bq:((w==1)?bk:bv))[c];
    }
    int e = t - 786432;
    if (e >= 0 && e < 38416){
        int h = e / 2401, r = e - h*2401;
        g_biasHIJ[e] = table[idx[r]*HEADS + h];
    }
}

// ---------------- K1: QKV GEMM (fp16 HMMA, 128x128x64 tiles) ----------------
#define BM 128
#define BN 128
#define BK 64
#define LDT 72    // BK + 8 halfs padding -> conflict-free ldmatrix

__global__ void __launch_bounds__(256,2) gemm_qkv(){
    extern __shared__ __align__(16) __half sm[];
    __half* As = sm;                          // [2][BM][LDT]
    __half* Bs = sm + 2*BM*LDT;               // [2][BN][LDT]
    const int tid  = threadIdx.x;
    const int lane = tid & 31, warp = tid >> 5;
    const int wm = (warp >> 2) * 64;          // 2 warps in M
    const int wn = (warp & 3) * 32;           // 4 warps in N
    const size_t rowA = (size_t)blockIdx.y * BM;   // M tiles on .y (N fastest -> A-tile L2 reuse)
    const size_t rowB = (size_t)blockIdx.x * BN;
    const __half* gA = g_H16  + rowA * KD;
    const __half* gB = g_WT16 + rowB * KD;

    auto load_tile = [&](int buf, int kc){
        #pragma unroll
        for (int i=0;i<4;i++){
            int c = tid + i*256;
            int r = c >> 3, o = (c & 7) * 8;
            cp_async16(&As[buf*(BM*LDT) + r*LDT + o], &gA[(size_t)r*KD + kc + o]);
        }
        #pragma unroll
        for (int i=0;i<4;i++){
            int c = tid + i*256;
            int r = c >> 3, o = (c & 7) * 8;
            cp_async16(&Bs[buf*(BN*LDT) + r*LDT + o], &gB[(size_t)r*KD + kc + o]);
        }
        asm volatile("cp.async.commit_group;\n" ::);
    };

    float acc[4][4][4];
    #pragma unroll
    for (int i=0;i<4;i++)
        #pragma unroll
        for (int j=0;j<4;j++)
            #pragma unroll
            for (int q=0;q<4;q++) acc[i][j][q] = 0.f;

    load_tile(0, 0);
    for (int ch=0; ch<8; ch++){
        if (ch < 7){
            load_tile((ch+1)&1, (ch+1)*BK);
            asm volatile("cp.async.wait_group 1;\n" ::);
        } else {
            asm volatile("cp.async.wait_group 0;\n" ::);
        }
        __syncthreads();
        const __half* At = &As[(ch&1)*(BM*LDT)];
        const __half* Bt = &Bs[(ch&1)*(BN*LDT)];

        // register-level double-buffered fragments: ldsm(kk+16) overlaps mma(kk)
        uint32_t a[2][4][4], b[2][2][4];
        auto LD = [&](int fb, int kk){
            #pragma unroll
            for (int mi=0;mi<4;mi++)
                ldsm_x4(a[fb][mi], &At[(wm + mi*16 + (lane&15))*LDT + kk + (lane>>4)*8]);
            #pragma unroll
            for (int nb=0;nb<2;nb++)
                ldsm_x4(b[fb][nb], &Bt[(wn + nb*16 + ((lane>>4)&1)*8 + (lane&7))*LDT
                                       + kk + ((lane>>3)&1)*8]);
        };
        LD(0, 0);
        #pragma unroll
        for (int kx=0; kx<4; kx++){
            if (kx < 3) LD((kx+1)&1, (kx+1)*16);
            const int fb = kx & 1;
            #pragma unroll
            for (int mi=0;mi<4;mi++)
                #pragma unroll
                for (int ni=0;ni<4;ni++)
                    mma16816(acc[mi][ni], a[fb][mi], &b[fb][ni>>1][(ni&1)*2]);
        }
        __syncthreads();
    }

    // epilogue: add bias, convert to fp16, scatter into [b][h][tok][d]
    const int rr = lane >> 2, cb = (lane & 3) * 2;
    #pragma unroll
    for (int mi=0;mi<4;mi++){
        int m0 = (int)rowA + wm + mi*16 + rr;
        int m1 = m0 + 8;
        int b0 = m0 / 49, t0 = m0 - b0*49;
        int b1 = m1 / 49, t1 = m1 - b1*49;
        #pragma unroll
        for (int ni=0;ni<4;ni++){
            int n = (int)rowB + wn + ni*8 + cb;
            int which = n >> 9, hh = (n >> 5) & 15, d = n & 31;
            float ba = g_biasf[n], bb = g_biasf[n+1];
            __half* dst = (which==0) ? g_Q : ((which==1) ? g_K : g_V);
            __half2 v01 = __floats2half2_rn(acc[mi][ni][0] + ba, acc[mi][ni][1] + bb);
            __half2 v23 = __floats2half2_rn(acc[mi][ni][2] + ba, acc[mi][ni][3] + bb);
            size_t a0 = (((size_t)b0*HEADS + hh)*49 + t0)*32 + d;
            size_t a1 = (((size_t)b1*HEADS + hh)*49 + t1)*32 + d;
            *reinterpret_cast<__half2*>(&dst[a0]) = v01;
            *reinterpret_cast<__half2*>(&dst[a1]) = v23;
        }
    }
}

// ---------------- K2: fused windowed attention ----------------
#define GROUP 8   // windows per block (same head -> bias tile reused)
#define LDV 40    // row stride in halfs

__global__ void __launch_bounds__(128) attn(float* __restrict__ out){
    const int h   = blockIdx.y;
    const int wg  = blockIdx.x;
    const int tid = threadIdx.x, lane = tid & 31, warp = tid >> 5;

    __shared__ __align__(16) float  sBias[2401];
    __shared__ __align__(16) __half sQ[2][64*LDV];   // rows 49-63 zero pad
    __shared__ __align__(16) __half sK[2][56*LDV];   // rows 49-55 zero pad
    __shared__ __align__(16) __half sV[2][64*LDV];   // rows 49-63 zero pad

    for (int e=tid; e<2401; e+=128) sBias[e] = g_biasHIJ[h*2401 + e];
    // zero only the padding rows (cp.async never touches them)
    for (int e=tid; e<15*LDV; e+=128){
        sQ[0][49*LDV+e] = sQ[1][49*LDV+e] = __float2half(0.f);
        sV[0][49*LDV+e] = sV[1][49*LDV+e] = __float2half(0.f);
    }
    for (int e=tid; e<7*LDV; e+=128){
        sK[0][49*LDV+e] = sK[1][49*LDV+e] = __float2half(0.f);
    }

    auto load_win = [&](int bf, int b){
        const size_t base = ((size_t)b*HEADS + h) * (49*32);
        #pragma unroll
        for (int i=0;i<5;i++){
            int idx = tid + i*128;
            if (idx < 588){
                int tsr = idx / 196;          // 0:Q 1:K 2:V
                int c   = idx - tsr*196;
                int row = c >> 2, part = c & 3;
                const __half* g = ((tsr==0)?g_Q:((tsr==1)?g_K:g_V)) + base + row*32 + part*8;
                __half* s = ((tsr==0)?&sQ[bf][0]:((tsr==1)?&sK[bf][0]:&sV[bf][0]))
                            + row*LDV + part*8;
                cp_async16(s, g);
            }
        }
        asm volatile("cp.async.commit_group;" ::);
    };

    const int rr = lane >> 2, cb = (lane & 3) * 2;
    const int row0 = warp*16 + rr;
    const int w0 = wg * GROUP;

    load_win(0, w0);

    #pragma unroll
    for (int wi=0; wi<GROUP; wi++){
        if (wi) __syncthreads();                       // compute wi-1 done before buffer reuse
        if (wi+1 < GROUP) load_win((wi+1)&1, w0+wi+1); // prefetch next window
        if (wi+1 < GROUP) asm volatile("cp.async.wait_group 1;" ::);
        else              asm volatile("cp.async.wait_group 0;" ::);
        __syncthreads();

        const __half* Qb = sQ[wi&1];
        const __half* Kb = sK[wi&1];
        const __half* Vb = sV[wi&1];
        const int b = w0 + wi;

        // ---- scores = Q K^T (m16 per warp, n=56 padded, k=32) ----
        uint32_t aq[2][4];
        ldsm_x4(aq[0], &Qb[(warp*16 + (lane&15))*LDV +      (lane>>4)*8]);
        ldsm_x4(aq[1], &Qb[(warp*16 + (lane&15))*LDV + 16 + (lane>>4)*8]);
        float sc[7][4];
        #pragma unroll
        for (int ni=0;ni<7;ni++){ sc[ni][0]=sc[ni][1]=sc[ni][2]=sc[ni][3]=0.f; }
        #pragma unroll
        for (int np=0;np<3;np++){        // n-pairs 0..5 via x4
            #pragma unroll
            for (int ko=0;ko<2;ko++){
                uint32_t bb[4];
                ldsm_x4(bb, &Kb[(np*16 + ((lane>>4)&1)*8 + (lane&7))*LDV
                                + ko*16 + ((lane>>3)&1)*8]);
                mma16816(sc[np*2],   aq[ko], &bb[0]);
                mma16816(sc[np*2+1], aq[ko], &bb[2]);
            }
        }
        #pragma unroll
        for (int ko=0;ko<2;ko++){        // ni=6 via x2
            uint32_t b2[2];
            ldsm_x2(b2, &Kb[(48 + (lane&7))*LDV + ko*16 + ((lane>>3)&1)*8]);
            mma16816(sc[6], aq[ko], b2);
        }

        // ---- scale + bias + mask, register softmax ----
        float m0=-1e30f, m1=-1e30f;
        #pragma unroll
        for (int ni=0;ni<7;ni++){
            #pragma unroll
            for (int c=0;c<2;c++){
                int col = ni*8 + cb + c;
                if (col < 49){
                    float bi0 = (row0   < 49) ? sBias[ row0   *49 + col] : 0.f;
                    float bi1 = (row0+8 < 49) ? sBias[(row0+8)*49 + col] : 0.f;
                    sc[ni][c]   = sc[ni][c]  *SCALE + bi0;
                    sc[ni][2+c] = sc[ni][2+c]*SCALE + bi1;
                    m0 = fmaxf(m0, sc[ni][c]);
                    m1 = fmaxf(m1, sc[ni][2+c]);
                } else {
                    sc[ni][c] = -1e30f; sc[ni][2+c] = -1e30f;
                }
            }
        }
        m0 = fmaxf(m0, __shfl_xor_sync(0xffffffffu, m0, 1));
        m0 = fmaxf(m0, __shfl_xor_sync(0xffffffffu, m0, 2));
        m1 = fmaxf(m1, __shfl_xor_sync(0xffffffffu, m1, 1));
        m1 = fmaxf(m1, __shfl_xor_sync(0xffffffffu, m1, 2));
        float s0=0.f, s1=0.f;
        #pragma unroll
        for (int ni=0;ni<7;ni++){
            #pragma unroll
            for (int c=0;c<2;c++){
                int col = ni*8 + cb + c;
                float p0, p1;
                if (col < 49){
                    p0 = __expf(sc[ni][c]   - m0);
                    p1 = __expf(sc[ni][2+c] - m1);
                } else { p0 = 0.f; p1 = 0.f; }
                sc[ni][c] = p0; sc[ni][2+c] = p1;
                s0 += p0; s1 += p1;
            }
        }
        s0 += __shfl_xor_sync(0xffffffffu, s0, 1);
        s0 += __shfl_xor_sync(0xffffffffu, s0, 2);
        s1 += __shfl_xor_sync(0xffffffffu, s1, 1);
        s1 += __shfl_xor_sync(0xffffffffu, s1, 2);

        // ---- ctx = P V : score C-frags repacked as A-frags, V via ldsm.trans ----
        float o[4][4];
        #pragma unroll
        for (int ni=0;ni<4;ni++){ o[ni][0]=o[ni][1]=o[ni][2]=o[ni][3]=0.f; }
        #pragma unroll
        for (int ks=0; ks<4; ks++){
            uint32_t pa[4];
            int f0 = 2*ks, f1 = 2*ks + 1;
            __half2 t0 = __floats2half2_rn(sc[f0][0], sc[f0][1]);
            __half2 t1 = __floats2half2_rn(sc[f0][2], sc[f0][3]);
            pa[0] = *reinterpret_cast<uint32_t*>(&t0);
            pa[1] = *reinterpret_cast<uint32_t*>(&t1);
            if (f1 < 7){
                __half2 t2 = __floats2half2_rn(sc[f1][0], sc[f1][1]);
                __half2 t3 = __floats2half2_rn(sc[f1][2], sc[f1][3]);
                pa[2] = *reinterpret_cast<uint32_t*>(&t2);
                pa[3] = *reinterpret_cast<uint32_t*>(&t3);
            } else { pa[2] = 0u; pa[3] = 0u; }
            #pragma unroll
            for (int nb=0;nb<2;nb++){
                uint32_t bb[4];
                ldsm_x4t(bb, &Vb[(ks*16 + (lane&15))*LDV + nb*16 + ((lane>>4)&1)*8]);
                mma16816(o[nb*2],   pa, &bb[0]);
                mma16816(o[nb*2+1], pa, &bb[2]);
            }
        }

        float inv0 = 1.f / s0, inv1 = 1.f / s1;
        #pragma unroll
        for (int ni=0;ni<4;ni++){
            int d = ni*8 + cb;
            if (row0 < 49){
                float2 r = make_float2(o[ni][0]*inv0, o[ni][1]*inv0);
                *reinterpret_cast<float2*>(&out[((size_t)b*49 + row0)*512 + h*32 + d]) = r;
            }
            if (row0 + 8 < 49){
                float2 r = make_float2(o[ni][2]*inv1, o[ni][3]*inv1);
                *reinterpret_cast<float2*>(&out[((size_t)b*49 + row0 + 8)*512 + h*32 + d]) = r;
            }
        }
    }
}

// ---------------- launch ----------------
extern "C" void kernel_launch(void* const* d_in, const int* in_sizes, int n_in,
                              void* d_out, int out_size){
    const float* hidden = (const float*)d_in[0];
    const float* Wq = (const float*)d_in[1];
    const float* bq = (const float*)d_in[2];
    const float* Wk = (const float*)d_in[3];
    const float* bk = (const float*)d_in[4];
    const float* Wv = (const float*)d_in[5];
    const float* bv = (const float*)d_in[6];
    const float* table = (const float*)d_in[7];
    const int*   idx   = (const int*)  d_in[8];
    float* out = (float*)d_out;

    const int gemm_smem = 2*(BM*LDT + BN*LDT)*(int)sizeof(__half);   // 73728
    cudaFuncSetAttribute(gemm_qkv, cudaFuncAttributeMaxDynamicSharedMemorySize, gemm_smem);

    cvt_hidden<<<50176, 256>>>(hidden);
    prep_all  <<<3223,  256>>>(Wq, bq, Wk, bk, Wv, bv, table, idx);
    gemm_qkv  <<<dim3(12, 1568), 256, gemm_smem>>>();   // N-tiles fastest -> A-tile L2 reuse
    attn      <<<dim3(512, 16), 128>>>(out);
}

// round 15
// speedup vs baseline: 1.1941x; 1.1526x over previous
#include <cuda_runtime.h>
#include <cuda_fp16.h>
#include <stdint.h>

#define NTOK   49
#define DIM    512
#define HEADS  16
#define HDIM   32
#define BATCH  4096
#define MROWS  200704          // BATCH*NTOK
#define KD     512
#define SCALE  0.17677669529663687f   // 1/sqrt(32)

// ---------------- scratch (static device arrays; no allocation) ----------------
__device__ __half g_H16 [102760448];   // hidden fp16 [MROWS][512]
__device__ __half g_WT16[786432];      // weights [n=1536][k=512] fp16 (transposed)
__device__ float  g_biasf[1536];       // packed bq|bk|bv
__device__ __half g_Q[102760448];      // [b][h][tok][d]
__device__ __half g_K[102760448];
__device__ __half g_V[102760448];
__device__ float  g_biasHIJ[38416];    // [h][i][j] gathered rel-pos bias

// ---------------- helpers ----------------
__device__ __forceinline__ uint32_t smem_u32(const void* p){
    return (uint32_t)__cvta_generic_to_shared(p);
}
__device__ __forceinline__ void cp_async16(void* s, const void* g){
    asm volatile("cp.async.cg.shared.global [%0], [%1], 16;\n"
                 :: "r"(smem_u32(s)), "l"(g));
}
__device__ __forceinline__ void ldsm_x4(uint32_t* r, const void* p){
    asm volatile("ldmatrix.sync.aligned.m8n8.x4.shared.b16 {%0,%1,%2,%3}, [%4];"
        : "=r"(r[0]),"=r"(r[1]),"=r"(r[2]),"=r"(r[3]) : "r"(smem_u32(p)));
}
__device__ __forceinline__ void ldsm_x4t(uint32_t* r, const void* p){
    asm volatile("ldmatrix.sync.aligned.m8n8.x4.trans.shared.b16 {%0,%1,%2,%3}, [%4];"
        : "=r"(r[0]),"=r"(r[1]),"=r"(r[2]),"=r"(r[3]) : "r"(smem_u32(p)));
}
__device__ __forceinline__ void ldsm_x2(uint32_t* r, const void* p){
    asm volatile("ldmatrix.sync.aligned.m8n8.x2.shared.b16 {%0,%1}, [%2];"
        : "=r"(r[0]),"=r"(r[1]) : "r"(smem_u32(p)));
}
__device__ __forceinline__ void mma16816(float* c, const uint32_t* a, const uint32_t* b){
    asm volatile("mma.sync.aligned.m16n8k16.row.col.f32.f16.f16.f32 "
        "{%0,%1,%2,%3},{%4,%5,%6,%7},{%8,%9},{%0,%1,%2,%3};"
        : "+f"(c[0]),"+f"(c[1]),"+f"(c[2]),"+f"(c[3])
        : "r"(a[0]),"r"(a[1]),"r"(a[2]),"r"(a[3]),"r"(b[0]),"r"(b[1]));
}

// ---------------- K0: convert hidden to fp16 ----------------
__global__ void cvt_hidden(const float* __restrict__ src){
    size_t i = (size_t)blockIdx.x * blockDim.x + threadIdx.x;
    const float4* s4 = reinterpret_cast<const float4*>(src);
    float4 f0 = s4[i*2], f1 = s4[i*2+1];
    __half2 h[4];
    h[0] = __floats2half2_rn(f0.x, f0.y);
    h[1] = __floats2half2_rn(f0.z, f0.w);
    h[2] = __floats2half2_rn(f1.x, f1.y);
    h[3] = __floats2half2_rn(f1.z, f1.w);
    *reinterpret_cast<uint4*>(&g_H16[i*8]) = *reinterpret_cast<uint4*>(h);
}

// ---------------- K0b: weights transpose + bias pack + rel-pos gather ----------------
__global__ void prep_all(const float* __restrict__ Wq, const float* __restrict__ bq,
                         const float* __restrict__ Wk, const float* __restrict__ bk,
                         const float* __restrict__ Wv, const float* __restrict__ bv,
                         const float* __restrict__ table, const int* __restrict__ idx){
    int t = blockIdx.x*256 + threadIdx.x;
    if (t < 786432){
        int n = t >> 9, k = t & 511;
        int w = n >> 9, col = n & 511;
        const float* W = (w==0)?Wq:((w==1)?Wk:Wv);
        g_WT16[t] = __float2half(W[k*512 + col]);
    }
    if (t < 1536){
        int w = t >> 9, c = t & 511;
        g_biasf[t] = ((w==0)?bq:((w==1)?bk:bv))[c];
    }
    int e = t - 786432;
    if (e >= 0 && e < 38416){
        int h = e / 2401, r = e - h*2401;
        g_biasHIJ[e] = table[idx[r]*HEADS + h];
    }
}

// ---------------- K1: QKV GEMM (fp16 HMMA, 128x128x64 tiles, 3-stage) ----------------
#define BM 128
#define BN 128
#define BK 64
#define LDT 72                       // BK + 8 halfs padding -> conflict-free ldmatrix
#define STG_A (BM*LDT)               // halfs per A stage
#define STG_B (BN*LDT)
#define STG   (STG_A + STG_B)
#define GSMEM (3*STG*(int)sizeof(__half))   // 110592 B -> 2 CTAs/SM

__global__ void __launch_bounds__(256,2) gemm_qkv(){
    extern __shared__ __align__(16) __half sm[];
    const int tid  = threadIdx.x;
    const int lane = tid & 31, warp = tid >> 5;
    const int wm = (warp >> 2) * 64;          // 2 warps in M
    const int wn = (warp & 3) * 32;           // 4 warps in N
    const size_t rowA = (size_t)blockIdx.y * BM;   // N fastest -> A-tile L2 reuse
    const size_t rowB = (size_t)blockIdx.x * BN;
    const __half* gA = g_H16  + rowA * KD;
    const __half* gB = g_WT16 + rowB * KD;

    auto load_tile = [&](int stg, int kc){
        __half* As = sm + stg*STG;
        __half* Bs = As + STG_A;
        #pragma unroll
        for (int i=0;i<4;i++){
            int c = tid + i*256;
            int r = c >> 3, o = (c & 7) * 8;
            cp_async16(&As[r*LDT + o], &gA[(size_t)r*KD + kc + o]);
        }
        #pragma unroll
        for (int i=0;i<4;i++){
            int c = tid + i*256;
            int r = c >> 3, o = (c & 7) * 8;
            cp_async16(&Bs[r*LDT + o], &gB[(size_t)r*KD + kc + o]);
        }
        asm volatile("cp.async.commit_group;\n" ::);
    };

    float acc[4][4][4];
    #pragma unroll
    for (int i=0;i<4;i++)
        #pragma unroll
        for (int j=0;j<4;j++)
            #pragma unroll
            for (int q=0;q<4;q++) acc[i][j][q] = 0.f;

    // preload S-1 = 2 stages; prefetch distance 2 (never aliases the read buffer)
    load_tile(0, 0);
    load_tile(1, BK);

    #pragma unroll
    for (int ch=0; ch<8; ch++){
        if (ch < 7) asm volatile("cp.async.wait_group 1;\n" ::);
        else        asm volatile("cp.async.wait_group 0;\n" ::);
        // one sync per chunk: publishes chunk ch AND retires chunk ch-1's readers
        __syncthreads();
        if (ch + 2 <= 7) load_tile((ch+2)%3, (ch+2)*BK);   // into chunk ch-1's buffer (retired)

        const __half* At = sm + (ch%3)*STG;
        const __half* Bt = At + STG_A;
        #pragma unroll
        for (int kx=0; kx<4; kx++){
            uint32_t a[4][4], b[2][4];
            #pragma unroll
            for (int mi=0;mi<4;mi++)
                ldsm_x4(a[mi], &At[(wm + mi*16 + (lane&15))*LDT + kx*16 + (lane>>4)*8]);
            #pragma unroll
            for (int nb=0;nb<2;nb++)
                ldsm_x4(b[nb], &Bt[(wn + nb*16 + ((lane>>4)&1)*8 + (lane&7))*LDT
                                   + kx*16 + ((lane>>3)&1)*8]);
            #pragma unroll
            for (int mi=0;mi<4;mi++)
                #pragma unroll
                for (int ni=0;ni<4;ni++)
                    mma16816(acc[mi][ni], a[mi], &b[ni>>1][(ni&1)*2]);
        }
    }

    // epilogue: add bias, convert to fp16, scatter into [b][h][tok][d]
    const int rr = lane >> 2, cb = (lane & 3) * 2;
    #pragma unroll
    for (int mi=0;mi<4;mi++){
        int m0 = (int)rowA + wm + mi*16 + rr;
        int m1 = m0 + 8;
        int b0 = m0 / 49, t0 = m0 - b0*49;
        int b1 = m1 / 49, t1 = m1 - b1*49;
        #pragma unroll
        for (int ni=0;ni<4;ni++){
            int n = (int)rowB + wn + ni*8 + cb;
            int which = n >> 9, hh = (n >> 5) & 15, d = n & 31;
            float ba = g_biasf[n], bb = g_biasf[n+1];
            __half* dst = (which==0) ? g_Q : ((which==1) ? g_K : g_V);
            __half2 v01 = __floats2half2_rn(acc[mi][ni][0] + ba, acc[mi][ni][1] + bb);
            __half2 v23 = __floats2half2_rn(acc[mi][ni][2] + ba, acc[mi][ni][3] + bb);
            size_t a0 = (((size_t)b0*HEADS + hh)*49 + t0)*32 + d;
            size_t a1 = (((size_t)b1*HEADS + hh)*49 + t1)*32 + d;
            *reinterpret_cast<__half2*>(&dst[a0]) = v01;
            *reinterpret_cast<__half2*>(&dst[a1]) = v23;
        }
    }
}

// ---------------- K2: fused windowed attention (2 windows / 256-thread block) ----------------
#define GROUP 8    // window-PAIRS per block
#define LDV 40     // row stride in halfs

// dynamic smem layout (bytes):
#define AB_BIAS 0                      // float[2401]           -> 9604, pad to 9632
#define AB_Q    9632                   // [2buf][2win][64*LDV] half -> 20480
#define AB_K    (9632+20480)           // [2buf][2win][56*LDV] half -> 17920
#define AB_V    (9632+20480+17920)     // [2buf][2win][64*LDV] half -> 20480
#define ASMEM   (9632+20480+17920+20480)   // 68512 B -> 3 CTAs/SM by smem

__global__ void __launch_bounds__(256,3) attn(float* __restrict__ out){
    extern __shared__ __align__(16) char asm_[];
    float*  sBias = reinterpret_cast<float*>(asm_ + AB_BIAS);
    __half* sQ    = reinterpret_cast<__half*>(asm_ + AB_Q);
    __half* sK    = reinterpret_cast<__half*>(asm_ + AB_K);
    __half* sV    = reinterpret_cast<__half*>(asm_ + AB_V);

    const int h   = blockIdx.y;
    const int wg  = blockIdx.x;
    const int tid = threadIdx.x, lane = tid & 31, warp = tid >> 5;
    const int win = warp >> 2;            // 0/1: which window of the pair
    const int w4  = warp & 3;             // row-quad within window

    for (int e=tid; e<2401; e+=256) sBias[e] = g_biasHIJ[h*2401 + e];
    // zero only the padding rows (cp.async never touches them)
    for (int e=tid; e<15*LDV; e+=256){
        #pragma unroll
        for (int s=0;s<4;s++){            // 2 buf x 2 win
            sQ[s*(64*LDV) + 49*LDV + e] = __float2half(0.f);
            sV[s*(64*LDV) + 49*LDV + e] = __float2half(0.f);
        }
    }
    for (int e=tid; e<7*LDV; e+=256){
        #pragma unroll
        for (int s=0;s<4;s++)
            sK[s*(56*LDV) + 49*LDV + e] = __float2half(0.f);
    }

    // load a window pair (b0, b0+1) into buffer bf
    auto load_pair = [&](int bf, int b0){
        #pragma unroll
        for (int i=0;i<5;i++){
            int idx = tid + i*256;
            if (idx < 1176){
                int wv  = idx / 588;                 // which window
                int rem = idx - wv*588;
                int tsr = rem / 196;                 // 0:Q 1:K 2:V
                int c   = rem - tsr*196;
                int row = c >> 2, part = c & 3;
                const size_t base = ((size_t)(b0+wv)*HEADS + h) * (49*32);
                const __half* g = ((tsr==0)?g_Q:((tsr==1)?g_K:g_V)) + base + row*32 + part*8;
                __half* s;
                if (tsr==0)      s = sQ + (bf*2+wv)*(64*LDV) + row*LDV + part*8;
                else if (tsr==1) s = sK + (bf*2+wv)*(56*LDV) + row*LDV + part*8;
                else             s = sV + (bf*2+wv)*(64*LDV) + row*LDV + part*8;
                cp_async16(s, g);
            }
        }
        asm volatile("cp.async.commit_group;" ::);
    };

    const int rr = lane >> 2, cb = (lane & 3) * 2;
    const int row0 = w4*16 + rr;
    const int w0 = wg * (2*GROUP);

    load_pair(0, w0);

    #pragma unroll
    for (int wi=0; wi<GROUP; wi++){
        if (wi) __syncthreads();                            // retire buffer (wi+1)&1 readers
        if (wi+1 < GROUP) load_pair((wi+1)&1, w0 + 2*(wi+1));
        if (wi+1 < GROUP) asm volatile("cp.async.wait_group 1;" ::);
        else              asm volatile("cp.async.wait_group 0;" ::);
        __syncthreads();

        const int bf = wi & 1;
        const __half* Qb = sQ + (bf*2+win)*(64*LDV);
        const __half* Kb = sK + (bf*2+win)*(56*LDV);
        const __half* Vb = sV + (bf*2+win)*(64*LDV);
        const int b = w0 + 2*wi + win;

        // ---- scores = Q K^T (m16 per warp-quad row, n=56 padded, k=32) ----
        uint32_t aq[2][4];
        ldsm_x4(aq[0], &Qb[(w4*16 + (lane&15))*LDV +      (lane>>4)*8]);
        ldsm_x4(aq[1], &Qb[(w4*16 + (lane&15))*LDV + 16 + (lane>>4)*8]);
        float sc[7][4];
        #pragma unroll
        for (int ni=0;ni<7;ni++){ sc[ni][0]=sc[ni][1]=sc[ni][2]=sc[ni][3]=0.f; }
        #pragma unroll
        for (int np=0;np<3;np++){
            #pragma unroll
            for (int ko=0;ko<2;ko++){
                uint32_t bb[4];
                ldsm_x4(bb, &Kb[(np*16 + ((lane>>4)&1)*8 + (lane&7))*LDV
                                + ko*16 + ((lane>>3)&1)*8]);
                mma16816(sc[np*2],   aq[ko], &bb[0]);
                mma16816(sc[np*2+1], aq[ko], &bb[2]);
            }
        }
        #pragma unroll
        for (int ko=0;ko<2;ko++){
            uint32_t b2[2];
            ldsm_x2(b2, &Kb[(48 + (lane&7))*LDV + ko*16 + ((lane>>3)&1)*8]);
            mma16816(sc[6], aq[ko], b2);
        }

        // ---- scale + bias + mask, register softmax ----
        float m0=-1e30f, m1=-1e30f;
        #pragma unroll
        for (int ni=0;ni<7;ni++){
            #pragma unroll
            for (int c=0;c<2;c++){
                int col = ni*8 + cb + c;
                if (col < 49){
                    float bi0 = (row0   < 49) ? sBias[ row0   *49 + col] : 0.f;
                    float bi1 = (row0+8 < 49) ? sBias[(row0+8)*49 + col] : 0.f;
                    sc[ni][c]   = sc[ni][c]  *SCALE + bi0;
                    sc[ni][2+c] = sc[ni][2+c]*SCALE + bi1;
                    m0 = fmaxf(m0, sc[ni][c]);
                    m1 = fmaxf(m1, sc[ni][2+c]);
                } else {
                    sc[ni][c] = -1e30f; sc[ni][2+c] = -1e30f;
                }
            }
        }
        m0 = fmaxf(m0, __shfl_xor_sync(0xffffffffu, m0, 1));
        m0 = fmaxf(m0, __shfl_xor_sync(0xffffffffu, m0, 2));
        m1 = fmaxf(m1, __shfl_xor_sync(0xffffffffu, m1, 1));
        m1 = fmaxf(m1, __shfl_xor_sync(0xffffffffu, m1, 2));
        float s0=0.f, s1=0.f;
        #pragma unroll
        for (int ni=0;ni<7;ni++){
            #pragma unroll
            for (int c=0;c<2;c++){
                int col = ni*8 + cb + c;
                float p0, p1;
                if (col < 49){
                    p0 = __expf(sc[ni][c]   - m0);
                    p1 = __expf(sc[ni][2+c] - m1);
                } else { p0 = 0.f; p1 = 0.f; }
                sc[ni][c] = p0; sc[ni][2+c] = p1;
                s0 += p0; s1 += p1;
            }
        }
        s0 += __shfl_xor_sync(0xffffffffu, s0, 1);
        s0 += __shfl_xor_sync(0xffffffffu, s0, 2);
        s1 += __shfl_xor_sync(0xffffffffu, s1, 1);
        s1 += __shfl_xor_sync(0xffffffffu, s1, 2);

        // ---- ctx = P V : score C-frags repacked as A-frags, V via ldsm.trans ----
        float o[4][4];
        #pragma unroll
        for (int ni=0;ni<4;ni++){ o[ni][0]=o[ni][1]=o[ni][2]=o[ni][3]=0.f; }
        #pragma unroll
        for (int ks=0; ks<4; ks++){
            uint32_t pa[4];
            int f0 = 2*ks, f1 = 2*ks + 1;
            __half2 t0 = __floats2half2_rn(sc[f0][0], sc[f0][1]);
            __half2 t1 = __floats2half2_rn(sc[f0][2], sc[f0][3]);
            pa[0] = *reinterpret_cast<uint32_t*>(&t0);
            pa[1] = *reinterpret_cast<uint32_t*>(&t1);
            if (f1 < 7){
                __half2 t2 = __floats2half2_rn(sc[f1][0], sc[f1][1]);
                __half2 t3 = __floats2half2_rn(sc[f1][2], sc[f1][3]);
                pa[2] = *reinterpret_cast<uint32_t*>(&t2);
                pa[3] = *reinterpret_cast<uint32_t*>(&t3);
            } else { pa[2] = 0u; pa[3] = 0u; }
            #pragma unroll
            for (int nb=0;nb<2;nb++){
                uint32_t bb[4];
                ldsm_x4t(bb, &Vb[(ks*16 + (lane&15))*LDV + nb*16 + ((lane>>4)&1)*8]);
                mma16816(o[nb*2],   pa, &bb[0]);
                mma16816(o[nb*2+1], pa, &bb[2]);
            }
        }

        float inv0 = 1.f / s0, inv1 = 1.f / s1;
        #pragma unroll
        for (int ni=0;ni<4;ni++){
            int d = ni*8 + cb;
            if (row0 < 49){
                float2 r = make_float2(o[ni][0]*inv0, o[ni][1]*inv0);
                *reinterpret_cast<float2*>(&out[((size_t)b*49 + row0)*512 + h*32 + d]) = r;
            }
            if (row0 + 8 < 49){
                float2 r = make_float2(o[ni][2]*inv1, o[ni][3]*inv1);
                *reinterpret_cast<float2*>(&out[((size_t)b*49 + row0 + 8)*512 + h*32 + d]) = r;
            }
        }
    }
}

// ---------------- launch ----------------
extern "C" void kernel_launch(void* const* d_in, const int* in_sizes, int n_in,
                              void* d_out, int out_size){
    const float* hidden = (const float*)d_in[0];
    const float* Wq = (const float*)d_in[1];
    const float* bq = (const float*)d_in[2];
    const float* Wk = (const float*)d_in[3];
    const float* bk = (const float*)d_in[4];
    const float* Wv = (const float*)d_in[5];
    const float* bv = (const float*)d_in[6];
    const float* table = (const float*)d_in[7];
    const int*   idx   = (const int*)  d_in[8];
    float* out = (float*)d_out;

    cudaFuncSetAttribute(gemm_qkv, cudaFuncAttributeMaxDynamicSharedMemorySize, GSMEM);
    cudaFuncSetAttribute(attn,     cudaFuncAttributeMaxDynamicSharedMemorySize, ASMEM);

    cvt_hidden<<<50176, 256>>>(hidden);
    prep_all  <<<3223,  256>>>(Wq, bq, Wk, bk, Wv, bv, table, idx);
    gemm_qkv  <<<dim3(12, 1568), 256, GSMEM>>>();   // N-tiles fastest -> A-tile L2 reuse
    attn      <<<dim3(BATCH/(2*GROUP), 16), 256, ASMEM>>>(out);
}